// round 14
// baseline (speedup 1.0000x reference)
#include <cuda_runtime.h>
#include <cstdint>

// Spiking1DLIFLayer: B=128, C=512, T=1024  (row=(b,c), serial recurrence over T)
//   mem = (mem*beta + x[t]) - spk_prev*Vth[c] ;  spk = mem > Vth[c]
// Pure HBM-bound stream (256MB in + 256MB out).
//
// R14: R10's measured-optimal 512B write-through bursts (GROUP=4; burst curve:
// 128B->99.1us, 512B->85.6us, 1KB->91.9us in-kernel) combined with R13's
// bit-packed spike accumulator (1 uint32 STS per tile, built in registers by
// predicate shift-or -- bit-exact). smem 31KB -> 14.6KB => ~13 blocks/SM
// (vs R10's 7): more reads in flight, smoother store interleave, 32x less
// smem write traffic. wt stores keep L2 clean at exit (no ~15us replay-
// boundary dirty-drain tax, established R2-R9).
// Numerics bit-identical to reference (rel_err 0.0 in R1-R13).

#define Bdim 128
#define Cdim 512
#define Tdim 1024
#define NT    32                 // threads per block == rows per block (1 warp)
#define TS    32                 // time-tile (floats) == bits per mask
#define F4    (TS / 4)           // 8 float4 per row per tile
#define PITCH (F4 + 1)           // 9 -> conflict-free input-buf access
#define NBUF  3
#define NTILES (Tdim / TS)       // 32
#define GROUP 4                  // tiles per write burst (4*128B = 512B/row)
#define BPITCH (GROUP + 1)       // 5 words/row -> conflict-free STS stride

__device__ __forceinline__ void cp16(uint32_t dst_smem, const float4* src) {
    asm volatile("cp.async.cg.shared.global [%0], [%1], 16;\n"
                 :: "r"(dst_smem), "l"(src));
}
__device__ __forceinline__ void cp_commit() {
    asm volatile("cp.async.commit_group;\n");
}
__device__ __forceinline__ void cp_wait2() {
    asm volatile("cp.async.wait_group 2;\n");
}
__device__ __forceinline__ void stwt(float4* p, float4 v) {
    asm volatile("st.global.wt.v4.f32 [%0], {%1, %2, %3, %4};\n"
                 :: "l"(p), "f"(v.x), "f"(v.y), "f"(v.z), "f"(v.w)
                 : "memory");
}
__device__ __forceinline__ float4 nib2f4(uint32_t word, int off) {
    float4 s;
    s.x = ((word >> (off + 0)) & 1u) ? 1.0f : 0.0f;
    s.y = ((word >> (off + 1)) & 1u) ? 1.0f : 0.0f;
    s.z = ((word >> (off + 2)) & 1u) ? 1.0f : 0.0f;
    s.w = ((word >> (off + 3)) & 1u) ? 1.0f : 0.0f;
    return s;
}

__global__ void __launch_bounds__(NT, 13)
lif_kernel(const float* __restrict__ x,
           const float* __restrict__ beta_p,
           const float* __restrict__ vth_p,
           float* __restrict__ out)
{
    __shared__ float4   tile[NBUF][NT * PITCH];    // input staging (13.8 KB)
    __shared__ uint32_t bits[NT * BPITCH];         // packed spikes (0.64 KB)

    const int tid = threadIdx.x;
    const int r0  = blockIdx.x * NT;
    const float beta = __ldg(beta_p);
    const float vth  = __ldg(vth_p + ((r0 + tid) & (Cdim - 1)));

    const float4* __restrict__ xg = (const float4*)x;
    float4* __restrict__ og = (float4*)out;
    const int row_f4 = Tdim / 4;                  // 256 float4 per global row

    // ---- prologue: preload tiles 0..2 ----
    #pragma unroll
    for (int p = 0; p < NBUF; ++p) {
        const int tcol0 = p * F4;
        uint32_t sbase = (uint32_t)__cvta_generic_to_shared(&tile[p][0]);
        #pragma unroll
        for (int i = 0; i < F4; ++i) {
            int idx = i * NT + tid;
            int row = idx >> 3;                   // idx / F4
            int col = idx & 7;                    // idx % F4
            cp16(sbase + (uint32_t)(row * PITCH + col) * 16u,
                 xg + (size_t)(r0 + row) * row_f4 + tcol0 + col);
        }
        cp_commit();
    }

    float mem = 0.0f;
    float rst = 0.0f;
    int b = 0;

    for (int it = 0; it < NTILES; ++it) {
        cp_wait2();                               // tile `it` landed
        __syncthreads();                          // nw=1: cheap; async->CTA vis

        // ---- recurrence: thread owns row `tid`, 32 steps -> 32-bit mask ----
        float4* mybuf = &tile[b][tid * PITCH];
        uint32_t mask = 0u;
        #pragma unroll
        for (int c = 0; c < F4; ++c) {
            float4 v = mybuf[c];
            #define LIF_STEP(XV, BIT)                                  \
                do {                                                   \
                    float t1 = __fmul_rn(mem, beta);                   \
                    float t2 = __fadd_rn(t1, (XV));                    \
                    mem = __fadd_rn(t2, -rst);                         \
                    bool p = (mem > vth);                              \
                    mask |= (p ? 1u : 0u) << (BIT);                    \
                    rst = p ? vth : 0.0f;                              \
                } while (0)
            LIF_STEP(v.x, c * 4 + 0);
            LIF_STEP(v.y, c * 4 + 1);
            LIF_STEP(v.z, c * 4 + 2);
            LIF_STEP(v.w, c * 4 + 3);
            #undef LIF_STEP
        }
        bits[tid * BPITCH + (it & (GROUP - 1))] = mask;   // 4B STS, no conflict
        __syncthreads();   // input-buf reads done (before refill) + bits visible

        // ---- every GROUP tiles: flush 512B/row write-through bursts ----
        if ((it & (GROUP - 1)) == (GROUP - 1)) {
            const int tbase = (it - (GROUP - 1)) * F4;   // first f4 col of group
            const int w0  = tid >> 3;                    // word index for lane
            const int off = (tid & 7) * 4;               // bit offset in word
            #pragma unroll
            for (int i = 0; i < NT; ++i) {
                // one warp-instruction per row: lanes cover 32 consecutive f4
                uint32_t w = bits[i * BPITCH + w0];          // 8-lane broadcast
                stwt(og + (size_t)(r0 + i) * row_f4 + tbase + tid,
                     nib2f4(w, off));
            }
        }

        // ---- refill buf b with tile it+3; always commit a group ----
        const int ip = it + NBUF;
        if (ip < NTILES) {
            const int tcol0 = ip * F4;
            uint32_t sbase = (uint32_t)__cvta_generic_to_shared(&tile[b][0]);
            #pragma unroll
            for (int i = 0; i < F4; ++i) {
                int idx = i * NT + tid;
                int row = idx >> 3;
                int col = idx & 7;
                cp16(sbase + (uint32_t)(row * PITCH + col) * 16u,
                     xg + (size_t)(r0 + row) * row_f4 + tcol0 + col);
            }
        }
        cp_commit();

        b = (b == NBUF - 1) ? 0 : b + 1;
    }
}

extern "C" void kernel_launch(void* const* d_in, const int* in_sizes, int n_in,
                              void* d_out, int out_size)
{
    const float* x    = (const float*)d_in[0];  // (128, 512, 1024) fp32
    const float* beta = (const float*)d_in[1];  // scalar fp32
    const float* vth  = (const float*)d_in[2];  // (512,) fp32
    float* out        = (float*)d_out;          // (128, 512, 1024) fp32

    lif_kernel<<<(Bdim * Cdim) / NT, NT>>>(x, beta, vth, out);
}

// round 15
// speedup vs baseline: 1.0951x; 1.0951x over previous
#include <cuda_runtime.h>
#include <cstdint>

// Spiking1DLIFLayer: B=128, C=512, T=1024  (row=(b,c), serial recurrence over T)
//   mem = (mem*beta + x[t]) - spk_prev*Vth[c] ;  spk = mem > Vth[c]
// Pure HBM-bound stream (256MB in + 256MB out).
//
// R15 = R10 (best: 92.3us timed) + refill-before-flush scheduling.
// Measured landscape: wt stores (only policy avoiding the ~15us replay-
// boundary dirty-L2 drain), 512B bursts optimal (128B:99.1 / 512B:85.6 /
// 1KB:91.9 in-kernel), fp32 smem accumulator (bit-pack = ALU explosion,
// R14), 7 blocks/SM sufficient (R11/R12). This round's single change: issue
// the next tile's cp.asyncs BEFORE the serial store burst, so reads are in
// flight during the flush instead of after it. Legal because the post-compute
// barrier already orders all reads of tile[b] before its refill, and the
// flush touches only acc. Numerics bit-identical (rel_err 0.0 in R1-R14).

#define Bdim 128
#define Cdim 512
#define Tdim 1024
#define NT    32                 // threads per block == rows per block (1 warp)
#define TS    32                 // time-tile (floats)
#define F4    (TS / 4)           // 8 float4 per row per tile
#define PITCH (F4 + 1)           // 9 -> conflict-free input-buf access
#define NBUF  3
#define NTILES (Tdim / TS)       // 32
#define GROUP 4                  // tiles per write burst (4*128B = 512B/row)
#define ACC_F4 (GROUP * F4)      // 32 float4 per row in accumulator
#define ACC_PITCH (ACC_F4 + 1)   // 33

__device__ __forceinline__ void cp16(uint32_t dst_smem, const float4* src) {
    asm volatile("cp.async.cg.shared.global [%0], [%1], 16;\n"
                 :: "r"(dst_smem), "l"(src));
}
__device__ __forceinline__ void cp_commit() {
    asm volatile("cp.async.commit_group;\n");
}
__device__ __forceinline__ void cp_wait2() {
    asm volatile("cp.async.wait_group 2;\n");
}
__device__ __forceinline__ void stwt(float4* p, float4 v) {
    asm volatile("st.global.wt.v4.f32 [%0], {%1, %2, %3, %4};\n"
                 :: "l"(p), "f"(v.x), "f"(v.y), "f"(v.z), "f"(v.w)
                 : "memory");
}

__global__ void __launch_bounds__(NT, 7)
lif_kernel(const float* __restrict__ x,
           const float* __restrict__ beta_p,
           const float* __restrict__ vth_p,
           float* __restrict__ out)
{
    __shared__ float4 tile[NBUF][NT * PITCH];      // input staging (13.8 KB)
    __shared__ float4 acc[NT * ACC_PITCH];         // spike accumulator (16.9 KB)

    const int tid = threadIdx.x;
    const int r0  = blockIdx.x * NT;
    const float beta = __ldg(beta_p);
    const float vth  = __ldg(vth_p + ((r0 + tid) & (Cdim - 1)));

    const float4* __restrict__ xg = (const float4*)x;
    float4* __restrict__ og = (float4*)out;
    const int row_f4 = Tdim / 4;                  // 256 float4 per global row

    // ---- prologue: preload tiles 0..2 ----
    #pragma unroll
    for (int p = 0; p < NBUF; ++p) {
        const int tcol0 = p * F4;
        uint32_t sbase = (uint32_t)__cvta_generic_to_shared(&tile[p][0]);
        #pragma unroll
        for (int i = 0; i < F4; ++i) {
            int idx = i * NT + tid;
            int row = idx >> 3;                   // idx / F4
            int col = idx & 7;                    // idx % F4
            cp16(sbase + (uint32_t)(row * PITCH + col) * 16u,
                 xg + (size_t)(r0 + row) * row_f4 + tcol0 + col);
        }
        cp_commit();
    }

    float mem = 0.0f;
    float rst = 0.0f;
    int b = 0;

    for (int it = 0; it < NTILES; ++it) {
        cp_wait2();                               // tile `it` landed
        __syncthreads();                          // nw=1: cheap; async->CTA vis

        // ---- recurrence: thread owns row `tid`, 32 steps ----
        float4* mybuf = &tile[b][tid * PITCH];
        float4* myacc = &acc[tid * ACC_PITCH + (it & (GROUP - 1)) * F4];
        #pragma unroll
        for (int c = 0; c < F4; ++c) {
            float4 v = mybuf[c];
            float4 s;
            #define LIF_STEP(XV, SV)                                   \
                do {                                                   \
                    float t1 = __fmul_rn(mem, beta);                   \
                    float t2 = __fadd_rn(t1, (XV));                    \
                    mem = __fadd_rn(t2, -rst);                         \
                    float spk = (mem > vth) ? 1.0f : 0.0f;             \
                    (SV) = spk;                                        \
                    rst = (mem > vth) ? vth : 0.0f;                    \
                } while (0)
            LIF_STEP(v.x, s.x);
            LIF_STEP(v.y, s.y);
            LIF_STEP(v.z, s.z);
            LIF_STEP(v.w, s.w);
            #undef LIF_STEP
            myacc[c] = s;
        }
        __syncthreads();   // all reads of tile[b] done + acc visible cross-thread

        // ---- refill buf b with tile it+3 FIRST (reads in flight during
        //      the store burst below); always commit one group per iter ----
        const int ip = it + NBUF;
        if (ip < NTILES) {
            const int tcol0 = ip * F4;
            uint32_t sbase = (uint32_t)__cvta_generic_to_shared(&tile[b][0]);
            #pragma unroll
            for (int i = 0; i < F4; ++i) {
                int idx = i * NT + tid;
                int row = idx >> 3;
                int col = idx & 7;
                cp16(sbase + (uint32_t)(row * PITCH + col) * 16u,
                     xg + (size_t)(r0 + row) * row_f4 + tcol0 + col);
            }
        }
        cp_commit();

        // ---- every GROUP tiles: flush 512B/row write-through bursts ----
        if ((it & (GROUP - 1)) == (GROUP - 1)) {
            const int tbase = (it - (GROUP - 1)) * F4;   // first f4 col of group
            #pragma unroll
            for (int i = 0; i < NT; ++i) {
                // one warp-instruction per row: lanes cover 32 consecutive f4
                stwt(og + (size_t)(r0 + i) * row_f4 + tbase + tid,
                     acc[i * ACC_PITCH + tid]);
            }
        }

        b = (b == NBUF - 1) ? 0 : b + 1;
    }
}

extern "C" void kernel_launch(void* const* d_in, const int* in_sizes, int n_in,
                              void* d_out, int out_size)
{
    const float* x    = (const float*)d_in[0];  // (128, 512, 1024) fp32
    const float* beta = (const float*)d_in[1];  // scalar fp32
    const float* vth  = (const float*)d_in[2];  // (512,) fp32
    float* out        = (float*)d_out;          // (128, 512, 1024) fp32

    lif_kernel<<<(Bdim * Cdim) / NT, NT>>>(x, beta, vth, out);
}

// round 16
// speedup vs baseline: 1.1212x; 1.0238x over previous
#include <cuda_runtime.h>
#include <cstdint>

// Spiking1DLIFLayer: B=128, C=512, T=1024  (row=(b,c), serial recurrence over T)
//   mem = (mem*beta + x[t]) - spk_prev*Vth[c] ;  spk = mem > Vth[c]
// Pure HBM-bound stream (256MB in + 256MB out).
//
// R15 = R10 (best: 92.3us timed) + refill-before-flush scheduling.
// Measured landscape: wt stores (only policy avoiding the ~15us replay-
// boundary dirty-L2 drain), 512B bursts optimal (128B:99.1 / 512B:85.6 /
// 1KB:91.9 in-kernel), fp32 smem accumulator (bit-pack = ALU explosion,
// R14), 7 blocks/SM sufficient (R11/R12). This round's single change: issue
// the next tile's cp.asyncs BEFORE the serial store burst, so reads are in
// flight during the flush instead of after it. Legal because the post-compute
// barrier already orders all reads of tile[b] before its refill, and the
// flush touches only acc. Numerics bit-identical (rel_err 0.0 in R1-R14).

#define Bdim 128
#define Cdim 512
#define Tdim 1024
#define NT    32                 // threads per block == rows per block (1 warp)
#define TS    32                 // time-tile (floats)
#define F4    (TS / 4)           // 8 float4 per row per tile
#define PITCH (F4 + 1)           // 9 -> conflict-free input-buf access
#define NBUF  3
#define NTILES (Tdim / TS)       // 32
#define GROUP 4                  // tiles per write burst (4*128B = 512B/row)
#define ACC_F4 (GROUP * F4)      // 32 float4 per row in accumulator
#define ACC_PITCH (ACC_F4 + 1)   // 33

__device__ __forceinline__ void cp16(uint32_t dst_smem, const float4* src) {
    asm volatile("cp.async.cg.shared.global [%0], [%1], 16;\n"
                 :: "r"(dst_smem), "l"(src));
}
__device__ __forceinline__ void cp_commit() {
    asm volatile("cp.async.commit_group;\n");
}
__device__ __forceinline__ void cp_wait2() {
    asm volatile("cp.async.wait_group 2;\n");
}
__device__ __forceinline__ void stwt(float4* p, float4 v) {
    asm volatile("st.global.wt.v4.f32 [%0], {%1, %2, %3, %4};\n"
                 :: "l"(p), "f"(v.x), "f"(v.y), "f"(v.z), "f"(v.w)
                 : "memory");
}

__global__ void __launch_bounds__(NT, 7)
lif_kernel(const float* __restrict__ x,
           const float* __restrict__ beta_p,
           const float* __restrict__ vth_p,
           float* __restrict__ out)
{
    __shared__ float4 tile[NBUF][NT * PITCH];      // input staging (13.8 KB)
    __shared__ float4 acc[NT * ACC_PITCH];         // spike accumulator (16.9 KB)

    const int tid = threadIdx.x;
    const int r0  = blockIdx.x * NT;
    const float beta = __ldg(beta_p);
    const float vth  = __ldg(vth_p + ((r0 + tid) & (Cdim - 1)));

    const float4* __restrict__ xg = (const float4*)x;
    float4* __restrict__ og = (float4*)out;
    const int row_f4 = Tdim / 4;                  // 256 float4 per global row

    // ---- prologue: preload tiles 0..2 ----
    #pragma unroll
    for (int p = 0; p < NBUF; ++p) {
        const int tcol0 = p * F4;
        uint32_t sbase = (uint32_t)__cvta_generic_to_shared(&tile[p][0]);
        #pragma unroll
        for (int i = 0; i < F4; ++i) {
            int idx = i * NT + tid;
            int row = idx >> 3;                   // idx / F4
            int col = idx & 7;                    // idx % F4
            cp16(sbase + (uint32_t)(row * PITCH + col) * 16u,
                 xg + (size_t)(r0 + row) * row_f4 + tcol0 + col);
        }
        cp_commit();
    }

    float mem = 0.0f;
    float rst = 0.0f;
    int b = 0;

    for (int it = 0; it < NTILES; ++it) {
        cp_wait2();                               // tile `it` landed
        __syncthreads();                          // nw=1: cheap; async->CTA vis

        // ---- recurrence: thread owns row `tid`, 32 steps ----
        float4* mybuf = &tile[b][tid * PITCH];
        float4* myacc = &acc[tid * ACC_PITCH + (it & (GROUP - 1)) * F4];
        #pragma unroll
        for (int c = 0; c < F4; ++c) {
            float4 v = mybuf[c];
            float4 s;
            #define LIF_STEP(XV, SV)                                   \
                do {                                                   \
                    float t1 = __fmul_rn(mem, beta);                   \
                    float t2 = __fadd_rn(t1, (XV));                    \
                    mem = __fadd_rn(t2, -rst);                         \
                    float spk = (mem > vth) ? 1.0f : 0.0f;             \
                    (SV) = spk;                                        \
                    rst = (mem > vth) ? vth : 0.0f;                    \
                } while (0)
            LIF_STEP(v.x, s.x);
            LIF_STEP(v.y, s.y);
            LIF_STEP(v.z, s.z);
            LIF_STEP(v.w, s.w);
            #undef LIF_STEP
            myacc[c] = s;
        }
        __syncthreads();   // all reads of tile[b] done + acc visible cross-thread

        // ---- refill buf b with tile it+3 FIRST (reads in flight during
        //      the store burst below); always commit one group per iter ----
        const int ip = it + NBUF;
        if (ip < NTILES) {
            const int tcol0 = ip * F4;
            uint32_t sbase = (uint32_t)__cvta_generic_to_shared(&tile[b][0]);
            #pragma unroll
            for (int i = 0; i < F4; ++i) {
                int idx = i * NT + tid;
                int row = idx >> 3;
                int col = idx & 7;
                cp16(sbase + (uint32_t)(row * PITCH + col) * 16u,
                     xg + (size_t)(r0 + row) * row_f4 + tcol0 + col);
            }
        }
        cp_commit();

        // ---- every GROUP tiles: flush 512B/row write-through bursts ----
        if ((it & (GROUP - 1)) == (GROUP - 1)) {
            const int tbase = (it - (GROUP - 1)) * F4;   // first f4 col of group
            #pragma unroll
            for (int i = 0; i < NT; ++i) {
                // one warp-instruction per row: lanes cover 32 consecutive f4
                stwt(og + (size_t)(r0 + i) * row_f4 + tbase + tid,
                     acc[i * ACC_PITCH + tid]);
            }
        }

        b = (b == NBUF - 1) ? 0 : b + 1;
    }
}

extern "C" void kernel_launch(void* const* d_in, const int* in_sizes, int n_in,
                              void* d_out, int out_size)
{
    const float* x    = (const float*)d_in[0];  // (128, 512, 1024) fp32
    const float* beta = (const float*)d_in[1];  // scalar fp32
    const float* vth  = (const float*)d_in[2];  // (512,) fp32
    float* out        = (float*)d_out;          // (128, 512, 1024) fp32

    lif_kernel<<<(Bdim * Cdim) / NT, NT>>>(x, beta, vth, out);
}